// round 6
// baseline (speedup 1.0000x reference)
#include <cuda_runtime.h>

// Problem constants (fixed by the reference):
//   B=4, C=32, H=64, W=64, K=64, pool block 2x2
#define KK     64
#define HW     4096
#define MAXN   4096      // k-major capacity per RF (actual support <= ~950)
#define NBC    128       // B*C
#define NTH    256

// Static device scratch (no allocation allowed).
// k-major list: bits[31:20]=pixel idx, bits[19:0]=rf quantized to 20 bits.
__device__ unsigned int g_list[KK * MAXN];        // 1 MB
__device__ int          g_cnt[KK];
// pixel-major list: slot j of pixel x at [j*HW + x] (coalesced over x).
// bits[31:26]=k, bits[25:0]=rf quantized to 26 bits.
__device__ unsigned int g_plist[KK * HW];         // 1 MB
__device__ int          g_pcnt[HW];

#define QS20     1048575.0f
#define INV_Q20  (1.0f / 1048575.0f)
#define QS26     67108863.0f
#define INV_Q26  (1.0f / 67108863.0f)

// ---------------------------------------------------------------------------
// Build 1: deterministic k-major compaction (for the denominators).
// One CTA per k; chunk counts + fixed-order scan => bit-identical list order.
// ---------------------------------------------------------------------------
__global__ __launch_bounds__(NTH) void build_klist(const float* __restrict__ rfs) {
    const int k   = blockIdx.x;
    const int tid = threadIdx.x;
    const float* __restrict__ r = rfs + k * HW;

    __shared__ int scan[NTH];

    float vals[16];
    const int base = tid * 16;
#pragma unroll
    for (int i = 0; i < 16; i += 4) {
        float4 v = *reinterpret_cast<const float4*>(r + base + i);
        vals[i] = v.x; vals[i + 1] = v.y; vals[i + 2] = v.z; vals[i + 3] = v.w;
    }
    int c = 0;
#pragma unroll
    for (int i = 0; i < 16; i++) c += (vals[i] > 0.0f);

    scan[tid] = c;
    __syncthreads();
#pragma unroll
    for (int off = 1; off < NTH; off <<= 1) {
        int t = (tid >= off) ? scan[tid - off] : 0;
        __syncthreads();
        scan[tid] += t;
        __syncthreads();
    }

    int pos = scan[tid] - c;  // exclusive prefix
    const int ob = k * MAXN;
#pragma unroll
    for (int i = 0; i < 16; i++) {
        if (vals[i] > 0.0f) {
            unsigned int q = (unsigned int)(vals[i] * QS20 + 0.5f);
            g_list[ob + pos] = ((unsigned int)(base + i) << 20) | q;
            pos++;
        }
    }
    if (tid == NTH - 1) g_cnt[k] = scan[NTH - 1];
}

// ---------------------------------------------------------------------------
// Build 2: pixel-major transposed list. One thread per pixel; k ascending
// => deterministic order. Slot layout [j*HW + x] so phase-2 loads coalesce.
// ---------------------------------------------------------------------------
__global__ __launch_bounds__(NTH) void build_plist(const float* __restrict__ rfs) {
    const int x = blockIdx.x * NTH + threadIdx.x;  // grid = HW/NTH = 16
    int n = 0;
#pragma unroll 4
    for (int k = 0; k < KK; k++) {
        const float v = rfs[k * HW + x];
        if (v > 0.0f) {
            g_plist[n * HW + x] =
                ((unsigned int)k << 26) | (unsigned int)(v * QS26 + 0.5f);
            n++;
        }
    }
    g_pcnt[x] = n;
}

// ---------------------------------------------------------------------------
// Main: one CTA per (b,c).
//   Phase 1: per-warp denominators over the k-major list -> inv_s[64].
//   Phase 2: per-pixel gather over the pixel-major list, accumulation in a
//            register (no scatter, no accumulator smem traffic).
//   Epilogue: 2x2 block max.
// All reductions/accumulations in fixed order => bitwise deterministic.
// Numerics: e/denom == exp(v-m)/(exp(-m)+Sum exp(v-m)) exactly; |v| small.
// ---------------------------------------------------------------------------
__global__ __launch_bounds__(NTH, 1) void rf_pool_main(const float* __restrict__ u,
                                                       float* __restrict__ out) {
    __shared__ float u_s[HW];
    __shared__ float h_s[HW];
    __shared__ float inv_s[KK];

    const int bc   = blockIdx.x;
    const int tid  = threadIdx.x;
    const int lane = tid & 31;
    const int wid  = tid >> 5;

    // load u tile (vectorized)
    const float4* __restrict__ ub4 = reinterpret_cast<const float4*>(u + bc * HW);
    for (int i = tid; i < HW / 4; i += NTH)
        reinterpret_cast<float4*>(u_s)[i] = ub4[i];
    __syncthreads();

    // ---- phase 1: denominators (warp-local, no block barriers inside) ----
#pragma unroll
    for (int kk = 0; kk < KK / 8; kk++) {
        const int k   = wid * (KK / 8) + kk;
        const int cnt = g_cnt[k];
        const unsigned int* __restrict__ ls = g_list + k * MAXN;

        float s = 0.0f;
        const int trips = (cnt + 31) >> 5;
#pragma unroll 4
        for (int j = 0; j < trips; j++) {
            const int t = lane + j * 32;
            unsigned int e = ls[t];  // in-bounds (capacity MAXN), value gated below
            if (t < cnt)
                s += __expf(u_s[e >> 20] * ((float)(e & 0xFFFFFu) * INV_Q20));
        }
#pragma unroll
        for (int o = 16; o; o >>= 1) s += __shfl_xor_sync(0xffffffffu, s, o);
        if (lane == 0) inv_s[k] = __fdividef(1.0f, 1.0f + s);
    }
    __syncthreads();

    // ---- phase 2: pixel-major gather, register accumulation ----
#pragma unroll
    for (int i = 0; i < HW / NTH; i++) {
        const int p  = tid + i * NTH;
        const float up = u_s[p];
        const int n  = g_pcnt[p];
        int m = n;  // warp-uniform trip count (max over warp)
#pragma unroll
        for (int o = 16; o; o >>= 1) {
            int t = __shfl_xor_sync(0xffffffffu, m, o);
            m = (t > m) ? t : m;
        }
        float acc = 0.0f;
#pragma unroll 4
        for (int j = 0; j < m; j++) {
            const unsigned int ent = g_plist[j * HW + p];  // coalesced, in-bounds
            if (j < n) {
                const int   k  = (int)(ent >> 26);
                const float rf = (float)(ent & 0x3FFFFFFu) * INV_Q26;
                acc += __expf(up * rf) * inv_s[k];
            }
        }
        h_s[p] = acc;
    }
    __syncthreads();

    // ---- epilogue: 2x2 block max pooling, (64,64) -> (32,32) ----
    float* __restrict__ ob = out + bc * 1024;
    for (int o = tid; o < 1024; o += NTH) {
        const int oy = o >> 5;
        const int ox = o & 31;
        const float* r0 = h_s + oy * 128 + ox * 2;
        ob[o] = fmaxf(fmaxf(r0[0], r0[1]), fmaxf(r0[64], r0[65]));
    }
}

extern "C" void kernel_launch(void* const* d_in, const int* in_sizes, int n_in,
                              void* d_out, int out_size) {
    const float* u   = (const float*)d_in[0];  // (B,C,H,W) = 524288 f32
    const float* rfs = (const float*)d_in[1];  // (K,H,W)   = 262144 f32
    float* out = (float*)d_out;                // (B,C,32,32) = 131072 f32

    build_klist<<<KK, NTH>>>(rfs);
    build_plist<<<HW / NTH, NTH>>>(rfs);
    rf_pool_main<<<NBC, NTH>>>(u, out);
}

// round 10
// speedup vs baseline: 2.4616x; 2.4616x over previous
#include <cuda_runtime.h>

// Problem constants (fixed by the reference):
//   B=4, C=32, H=64, W=64, K=64, pool block 2x2
#define KK     64
#define HW     4096
#define MAXN   1024      // k-major capacity per RF (actual support <= ~950)
#define NBC    128       // B*C
#define NTH    256

// Static device scratch (no allocation allowed).
// k-major list: bits[31:20]=pixel idx, bits[19:0]=rf quantized to 20 bits.
__device__ unsigned int g_list[KK * MAXN];        // 256 KB
__device__ int          g_cnt[KK];
// pixel-major list: slot j of pixel x at [j*HW + x] (coalesced over x).
// bits[31:26]=k, bits[25:0]=rf quantized to 26 bits.
__device__ unsigned int g_plist[KK * HW];         // 1 MB
__device__ int          g_pcnt[HW];
// per-(bc,k) inverse denominators
__device__ float        g_inv[NBC * KK];          // 32 KB

#define QS20     1048575.0f
#define INV_Q20  (1.0f / 1048575.0f)
#define QS26     67108863.0f
#define INV_Q26  (1.0f / 67108863.0f)

// ---------------------------------------------------------------------------
// Build (merged): blocks [0,64) build the k-major lists (shuffle-scan
// compaction, 2 barriers); blocks [64,80) build the pixel-major lists
// (k ascending per pixel). Fixed orders => bit-identical lists every call.
// ---------------------------------------------------------------------------
__global__ __launch_bounds__(NTH) void build_all(const float* __restrict__ rfs) {
    const int tid  = threadIdx.x;
    const int lane = tid & 31;
    const int wid  = tid >> 5;

    if (blockIdx.x < KK) {
        // ---- k-major compaction for k = blockIdx.x ----
        const int k = blockIdx.x;
        const float* __restrict__ r = rfs + k * HW;

        __shared__ int wsum[NTH / 32];
        __shared__ int woff[NTH / 32];

        float vals[16];
        const int base = tid * 16;
#pragma unroll
        for (int i = 0; i < 16; i += 4) {
            float4 v = *reinterpret_cast<const float4*>(r + base + i);
            vals[i] = v.x; vals[i + 1] = v.y; vals[i + 2] = v.z; vals[i + 3] = v.w;
        }
        int c = 0;
#pragma unroll
        for (int i = 0; i < 16; i++) c += (vals[i] > 0.0f);

        // warp inclusive scan of chunk counts
        int inc = c;
#pragma unroll
        for (int off = 1; off < 32; off <<= 1) {
            int t = __shfl_up_sync(0xffffffffu, inc, off);
            if (lane >= off) inc += t;
        }
        if (lane == 31) wsum[wid] = inc;
        __syncthreads();
        if (wid == 0) {
            int v = (lane < NTH / 32) ? wsum[lane] : 0;
#pragma unroll
            for (int off = 1; off < NTH / 32; off <<= 1) {
                int t = __shfl_up_sync(0xffffffffu, v, off);
                if (lane >= off) v += t;
            }
            if (lane < NTH / 32) woff[lane] = v - wsum[lane];  // exclusive
            if (lane == NTH / 32 - 1) g_cnt[k] = v;            // total
        }
        __syncthreads();

        int pos = woff[wid] + (inc - c);  // exclusive prefix across block
        const int ob = k * MAXN;
#pragma unroll
        for (int i = 0; i < 16; i++) {
            if (vals[i] > 0.0f) {
                unsigned int q = (unsigned int)(vals[i] * QS20 + 0.5f);
                if (pos < MAXN)
                    g_list[ob + pos] = ((unsigned int)(base + i) << 20) | q;
                pos++;
            }
        }
    } else {
        // ---- pixel-major list for 256 pixels ----
        const int x = (blockIdx.x - KK) * NTH + tid;
        int n = 0;
#pragma unroll 4
        for (int k = 0; k < KK; k++) {
            const float v = rfs[k * HW + x];
            if (v > 0.0f) {
                g_plist[n * HW + x] =
                    ((unsigned int)k << 26) | (unsigned int)(v * QS26 + 0.5f);
                n++;
            }
        }
        g_pcnt[x] = n;
    }
}

// ---------------------------------------------------------------------------
// Denominators: grid = NBC*4. CTA = (bc, quartet q of 16 k's); u tile in
// smem; each warp owns 2 k's, warp-shuffle reduce, no mainloop barriers.
// Numerics: e/denom == exp(v-m)/(exp(-m)+Sum exp(v-m)) exactly; |v| small.
// ---------------------------------------------------------------------------
__global__ __launch_bounds__(NTH) void denom_kernel(const float* __restrict__ u) {
    __shared__ float u_s[HW];

    const int bc   = blockIdx.x >> 2;
    const int q    = blockIdx.x & 3;
    const int tid  = threadIdx.x;
    const int lane = tid & 31;
    const int wid  = tid >> 5;

    const float4* __restrict__ ub4 = reinterpret_cast<const float4*>(u + bc * HW);
#pragma unroll
    for (int i = 0; i < HW / 4 / NTH; i++)
        reinterpret_cast<float4*>(u_s)[tid + i * NTH] = ub4[tid + i * NTH];
    __syncthreads();

#pragma unroll
    for (int kk = 0; kk < 2; kk++) {
        const int k   = q * 16 + wid * 2 + kk;
        const int cnt = g_cnt[k];
        const unsigned int* __restrict__ ls = g_list + k * MAXN;

        float s = 0.0f;
        const int trips = (cnt + 31) >> 5;
#pragma unroll 4
        for (int j = 0; j < trips; j++) {
            const int t = lane + j * 32;
            const unsigned int e = ls[t];  // always in-bounds (capacity MAXN)
            const float ev =
                __expf(u_s[e >> 20] * ((float)(e & 0xFFFFFu) * INV_Q20));
            s += (t < cnt) ? ev : 0.0f;
        }
#pragma unroll
        for (int o = 16; o; o >>= 1) s += __shfl_xor_sync(0xffffffffu, s, o);
        if (lane == 0) g_inv[bc * KK + k] = __fdividef(1.0f, 1.0f + s);
    }
}

// ---------------------------------------------------------------------------
// Gather + pool: grid = NBC*4. CTA = (bc, 8 output rows). Each thread owns
// one 2x2 block: 4 register accumulators, interleaved over the 4 pixels so
// the j-loop has 4-way independent LDG->MUFU->FMA chains. Unconditional list
// loads (in-bounds: j < 64), predicated accumulate. Fixed order per pixel.
// ---------------------------------------------------------------------------
__global__ __launch_bounds__(NTH) void gather_kernel(const float* __restrict__ u,
                                                     float* __restrict__ out) {
    __shared__ float inv_s[KK];

    const int bc  = blockIdx.x >> 2;
    const int rg  = blockIdx.x & 3;
    const int tid = threadIdx.x;

    if (tid < KK) inv_s[tid] = g_inv[bc * KK + tid];
    __syncthreads();

    const int o   = rg * 256 + tid;       // output index in [0,1024)
    const int oy  = o >> 5;
    const int ox  = o & 31;
    const int p00 = oy * 128 + ox * 2;    // top-left pixel of the 2x2 block

    const float* __restrict__ ub = u + bc * HW;
    const float2 ua = *reinterpret_cast<const float2*>(ub + p00);
    const float2 uc = *reinterpret_cast<const float2*>(ub + p00 + 64);
    const float up[4]  = {ua.x, ua.y, uc.x, uc.y};
    const int   px[4]  = {p00, p00 + 1, p00 + 64, p00 + 65};

    int n[4];
#pragma unroll
    for (int i = 0; i < 4; i++) n[i] = g_pcnt[px[i]];
    int mx = n[0];
#pragma unroll
    for (int i = 1; i < 4; i++) mx = (n[i] > mx) ? n[i] : mx;

    float acc[4] = {0.f, 0.f, 0.f, 0.f};
#pragma unroll 2
    for (int j = 0; j < mx; j++) {
        const unsigned int* __restrict__ row = g_plist + j * HW;
#pragma unroll
        for (int i = 0; i < 4; i++) {
            const unsigned int ent = row[px[i]];   // in-bounds: j < 64
            const int   kk = (int)(ent >> 26);
            const float rf = (float)(ent & 0x3FFFFFFu) * INV_Q26;
            const float e  = __expf(up[i] * rf) * inv_s[kk];
            acc[i] += (j < n[i]) ? e : 0.0f;
        }
    }

    out[bc * 1024 + o] =
        fmaxf(fmaxf(acc[0], acc[1]), fmaxf(acc[2], acc[3]));
}

extern "C" void kernel_launch(void* const* d_in, const int* in_sizes, int n_in,
                              void* d_out, int out_size) {
    const float* u   = (const float*)d_in[0];  // (B,C,H,W) = 524288 f32
    const float* rfs = (const float*)d_in[1];  // (K,H,W)   = 262144 f32
    float* out = (float*)d_out;                // (B,C,32,32) = 131072 f32

    build_all<<<KK + HW / NTH, NTH>>>(rfs);    // 80 CTAs
    denom_kernel<<<NBC * 4, NTH>>>(u);         // 512 CTAs
    gather_kernel<<<NBC * 4, NTH>>>(u, out);   // 512 CTAs
}

// round 11
// speedup vs baseline: 2.8346x; 1.1515x over previous
#include <cuda_runtime.h>

// Problem constants (fixed by the reference):
//   B=4, C=32, H=64, W=64, K=64, pool block 2x2
#define KK     64
#define HW     4096
#define MAXN   1024      // k-major capacity per RF (actual support <= ~950)
#define NBC    128       // B*C
#define NTH    256

// Static device scratch (no allocation allowed).
// k-major list: bits[31:20]=pixel idx, bits[19:0]=rf quantized to 20 bits.
__device__ unsigned int g_list[KK * MAXN];        // 256 KB
__device__ int          g_cnt[KK];
// pixel-major list: slot j of pixel x at [j*HW + x] (coalesced over x).
// bits[31:26]=k, bits[25:0]=rf quantized to 26 bits.
__device__ unsigned int g_plist[KK * HW];         // 1 MB
__device__ int          g_pcnt[HW];
// per-(bc,k) inverse denominators
__device__ float        g_inv[NBC * KK];          // 32 KB

#define QS20     1048575.0f
#define INV_Q20  (1.0f / 1048575.0f)
#define QS26     67108863.0f
#define INV_Q26  (1.0f / 67108863.0f)

// ---------------------------------------------------------------------------
// Build (merged, 96 CTAs):
//   blocks [0,64):  k-major list compaction (shuffle scan, 2 barriers).
//   blocks [64,96): pixel-major lists, 128 pixels/CTA, TWO threads per pixel
//                   (halves of the k-range), each preloading its 32 rf values
//                   into registers => MLP 32, one memory-latency trip.
// Fixed orders => bit-identical lists every call.
// ---------------------------------------------------------------------------
__global__ __launch_bounds__(NTH) void build_all(const float* __restrict__ rfs) {
    const int tid  = threadIdx.x;
    const int lane = tid & 31;
    const int wid  = tid >> 5;

    if (blockIdx.x < KK) {
        // ---- k-major compaction for k = blockIdx.x ----
        const int k = blockIdx.x;
        const float* __restrict__ r = rfs + k * HW;

        __shared__ int wsum[NTH / 32];
        __shared__ int woff[NTH / 32];

        float vals[16];
        const int base = tid * 16;
#pragma unroll
        for (int i = 0; i < 16; i += 4) {
            float4 v = *reinterpret_cast<const float4*>(r + base + i);
            vals[i] = v.x; vals[i + 1] = v.y; vals[i + 2] = v.z; vals[i + 3] = v.w;
        }
        int c = 0;
#pragma unroll
        for (int i = 0; i < 16; i++) c += (vals[i] > 0.0f);

        int inc = c;  // warp inclusive scan
#pragma unroll
        for (int off = 1; off < 32; off <<= 1) {
            int t = __shfl_up_sync(0xffffffffu, inc, off);
            if (lane >= off) inc += t;
        }
        if (lane == 31) wsum[wid] = inc;
        __syncthreads();
        if (wid == 0) {
            int v = (lane < NTH / 32) ? wsum[lane] : 0;
#pragma unroll
            for (int off = 1; off < NTH / 32; off <<= 1) {
                int t = __shfl_up_sync(0xffffffffu, v, off);
                if (lane >= off) v += t;
            }
            if (lane < NTH / 32) woff[lane] = v - wsum[lane];
            if (lane == NTH / 32 - 1) g_cnt[k] = v;
        }
        __syncthreads();

        int pos = woff[wid] + (inc - c);
        const int ob = k * MAXN;
#pragma unroll
        for (int i = 0; i < 16; i++) {
            if (vals[i] > 0.0f) {
                unsigned int q = (unsigned int)(vals[i] * QS20 + 0.5f);
                if (pos < MAXN)
                    g_list[ob + pos] = ((unsigned int)(base + i) << 20) | q;
                pos++;
            }
        }
    } else {
        // ---- pixel-major lists: 128 pixels, 2 threads/pixel ----
        __shared__ int cnt0[128];

        const int pl = tid & 127;                      // local pixel
        const int h  = tid >> 7;                       // k-half: 0 or 1
        const int p  = (blockIdx.x - KK) * 128 + pl;   // global pixel
        const int kb = h * 32;                         // k base for this half

        float vals[32];
#pragma unroll
        for (int i = 0; i < 32; i++)                   // 32 independent loads
            vals[i] = rfs[(kb + i) * HW + p];

        int c = 0;
#pragma unroll
        for (int i = 0; i < 32; i++) c += (vals[i] > 0.0f);

        if (h == 0) cnt0[pl] = c;
        __syncthreads();

        int n = h ? cnt0[pl] : 0;                      // start position
#pragma unroll
        for (int i = 0; i < 32; i++) {
            if (vals[i] > 0.0f) {
                g_plist[n * HW + p] = ((unsigned int)(kb + i) << 26) |
                                      (unsigned int)(vals[i] * QS26 + 0.5f);
                n++;
            }
        }
        if (h) g_pcnt[p] = n;                          // total count
    }
}

// ---------------------------------------------------------------------------
// Denominators: grid = NBC*8 (1024 CTAs). CTA = (bc, octet of 8 k's); u tile
// in smem; each warp owns ONE k, warp-shuffle reduce, no mainloop barriers.
// Numerics: e/denom == exp(v-m)/(exp(-m)+Sum exp(v-m)) exactly; |v| small.
// ---------------------------------------------------------------------------
__global__ __launch_bounds__(NTH) void denom_kernel(const float* __restrict__ u) {
    __shared__ float u_s[HW];

    const int bc   = blockIdx.x >> 3;
    const int oct  = blockIdx.x & 7;
    const int tid  = threadIdx.x;
    const int lane = tid & 31;
    const int wid  = tid >> 5;

    const float4* __restrict__ ub4 = reinterpret_cast<const float4*>(u + bc * HW);
#pragma unroll
    for (int i = 0; i < HW / 4 / NTH; i++)
        reinterpret_cast<float4*>(u_s)[tid + i * NTH] = ub4[tid + i * NTH];
    __syncthreads();

    const int k   = oct * 8 + wid;
    const int cnt = g_cnt[k];
    const unsigned int* __restrict__ ls = g_list + k * MAXN;

    float s = 0.0f;
    const int trips = (cnt + 31) >> 5;
#pragma unroll 4
    for (int j = 0; j < trips; j++) {
        const int t = lane + j * 32;
        const unsigned int e = ls[t];  // in-bounds (capacity MAXN); idx <= 4095
        const float ev = __expf(u_s[e >> 20] * ((float)(e & 0xFFFFFu) * INV_Q20));
        s += (t < cnt) ? ev : 0.0f;
    }
#pragma unroll
    for (int o = 16; o; o >>= 1) s += __shfl_xor_sync(0xffffffffu, s, o);
    if (lane == 0) g_inv[bc * KK + k] = __fdividef(1.0f, 1.0f + s);
}

// ---------------------------------------------------------------------------
// Gather + pool: grid = NBC*8, 128 threads. Each thread owns one 2x2 output
// block: 4 register accumulators, uint2 loads for the adjacent pixel pairs,
// 4-way independent LDG->MUFU->FMA chains, unroll 4 on the j-loop.
// Fixed per-pixel order => deterministic.
// ---------------------------------------------------------------------------
__global__ __launch_bounds__(128) void gather_kernel(const float* __restrict__ u,
                                                     float* __restrict__ out) {
    __shared__ float inv_s[KK];

    const int bc  = blockIdx.x >> 3;
    const int rg  = blockIdx.x & 7;
    const int tid = threadIdx.x;

    if (tid < KK) inv_s[tid] = g_inv[bc * KK + tid];
    __syncthreads();

    const int o   = rg * 128 + tid;       // output index in [0,1024)
    const int oy  = o >> 5;
    const int ox  = o & 31;
    const int p00 = oy * 128 + ox * 2;    // top-left pixel of the 2x2 block

    const float* __restrict__ ub = u + bc * HW;
    const float2 ua = *reinterpret_cast<const float2*>(ub + p00);
    const float2 uc = *reinterpret_cast<const float2*>(ub + p00 + 64);
    const float up[4] = {ua.x, ua.y, uc.x, uc.y};

    int n[4];
    {
        const int2 na = *reinterpret_cast<const int2*>(g_pcnt + p00);
        const int2 nb = *reinterpret_cast<const int2*>(g_pcnt + p00 + 64);
        n[0] = na.x; n[1] = na.y; n[2] = nb.x; n[3] = nb.y;
    }
    int mx = n[0];
#pragma unroll
    for (int i = 1; i < 4; i++) mx = (n[i] > mx) ? n[i] : mx;

    float acc[4] = {0.f, 0.f, 0.f, 0.f};
#pragma unroll 4
    for (int j = 0; j < mx; j++) {
        const unsigned int* __restrict__ row = g_plist + j * HW + p00;
        const uint2 ea = *reinterpret_cast<const uint2*>(row);        // px0,px1
        const uint2 eb = *reinterpret_cast<const uint2*>(row + 64);   // px2,px3
        const unsigned int ent[4] = {ea.x, ea.y, eb.x, eb.y};
#pragma unroll
        for (int i = 0; i < 4; i++) {
            const float rf = (float)(ent[i] & 0x3FFFFFFu) * INV_Q26;
            const float e  = __expf(up[i] * rf) * inv_s[ent[i] >> 26];
            acc[i] += (j < n[i]) ? e : 0.0f;
        }
    }

    out[bc * 1024 + o] = fmaxf(fmaxf(acc[0], acc[1]), fmaxf(acc[2], acc[3]));
}

extern "C" void kernel_launch(void* const* d_in, const int* in_sizes, int n_in,
                              void* d_out, int out_size) {
    const float* u   = (const float*)d_in[0];  // (B,C,H,W) = 524288 f32
    const float* rfs = (const float*)d_in[1];  // (K,H,W)   = 262144 f32
    float* out = (float*)d_out;                // (B,C,32,32) = 131072 f32

    build_all<<<KK + HW / 128, NTH>>>(rfs);    // 64 + 32 = 96 CTAs
    denom_kernel<<<NBC * 8, NTH>>>(u);         // 1024 CTAs
    gather_kernel<<<NBC * 8, 128>>>(u, out);   // 1024 CTAs
}